// round 1
// baseline (speedup 1.0000x reference)
#include <cuda_runtime.h>
#include <cuda_bf16.h>

#define Bq 8
#define Nq 1024
#define Cq 768
#define Hq 12
#define HDq 64
#define Rq 16
#define ROWS (Bq*Nq)          // 8192
#define SCALE 0.125f          // 64^-0.5

// ---------------- scratch (device globals; no allocation allowed) ----------------
__device__ float g_q[Bq*Hq*Nq*HDq];       // [B,H,N,HD]
__device__ float g_k[Bq*Hq*Nq*HDq];
__device__ float g_v[Bq*Hq*Nq*HDq];
__device__ float g_att[ROWS*Cq];          // [B,N,C]
__device__ float g_xa[3][ROWS*Rq];        // x @ la_{q,k,v}

// ---------------- kernel 1: x @ la for q,k,v ----------------
__global__ void lora_xa_kernel(const float* __restrict__ X,
                               const float* __restrict__ la_q,
                               const float* __restrict__ la_k,
                               const float* __restrict__ la_v) {
    __shared__ float xs[16][Cq];   // 48KB
    int rowBase = blockIdx.x * 16;
    for (int l = threadIdx.x; l < 16 * Cq; l += 256) {
        int r = l / Cq, c = l % Cq;
        xs[r][c] = X[(rowBase + r) * Cq + c];
    }
    __syncthreads();
    int r = threadIdx.x >> 4;      // 0..15 row
    int c = threadIdx.x & 15;      // 0..15 rank col
    float aq = 0.f, ak = 0.f, av = 0.f;
    #pragma unroll 4
    for (int k = 0; k < Cq; k++) {
        float xv = xs[r][k];
        aq = fmaf(xv, la_q[k * Rq + c], aq);
        ak = fmaf(xv, la_k[k * Rq + c], ak);
        av = fmaf(xv, la_v[k * Rq + c], av);
    }
    int row = rowBase + r;
    g_xa[0][row * Rq + c] = aq;
    g_xa[1][row * Rq + c] = ak;
    g_xa[2][row * Rq + c] = av;
}

// ---------------- kernel 2: q/k/v = x@W + bw*(xa@lb), write head-split ----------------
#define BM 64
#define BN 64
#define BK 16
__global__ void proj_kernel(const float* __restrict__ X,
                            const float* __restrict__ W,
                            const float* __restrict__ lb,
                            const float* __restrict__ bw,
                            int type) {
    __shared__ float As[BK][BM];
    __shared__ float Bs[BK][BN];
    int tx = threadIdx.x & 15, ty = threadIdx.x >> 4;
    int rowBase = blockIdx.y * BM;
    int colBase = blockIdx.x * BN;
    float acc[4][4] = {};
    for (int k0 = 0; k0 < Cq; k0 += BK) {
        #pragma unroll
        for (int i = 0; i < 4; i++) {
            int l = threadIdx.x + 256 * i;              // 0..1023
            int m = l >> 4, kk = l & 15;
            As[kk][m] = X[(rowBase + m) * Cq + k0 + kk];
        }
        #pragma unroll
        for (int i = 0; i < 4; i++) {
            int l = threadIdx.x + 256 * i;
            int col = l & 63, kk = l >> 6;
            Bs[kk][col] = W[(k0 + kk) * Cq + colBase + col];
        }
        __syncthreads();
        #pragma unroll
        for (int kk = 0; kk < BK; kk++) {
            float a[4], b[4];
            #pragma unroll
            for (int ii = 0; ii < 4; ii++) a[ii] = As[kk][ty * 4 + ii];
            #pragma unroll
            for (int jj = 0; jj < 4; jj++) b[jj] = Bs[kk][tx * 4 + jj];
            #pragma unroll
            for (int ii = 0; ii < 4; ii++)
                #pragma unroll
                for (int jj = 0; jj < 4; jj++)
                    acc[ii][jj] = fmaf(a[ii], b[jj], acc[ii][jj]);
        }
        __syncthreads();
    }
    // LoRA epilogue
    float w = bw[type];
    const float* xa = g_xa[type];
    float lora[4][4] = {};
    #pragma unroll
    for (int r = 0; r < Rq; r++) {
        float a[4], b[4];
        #pragma unroll
        for (int ii = 0; ii < 4; ii++) a[ii] = xa[(rowBase + ty * 4 + ii) * Rq + r];
        #pragma unroll
        for (int jj = 0; jj < 4; jj++) b[jj] = lb[r * Cq + colBase + tx * 4 + jj];
        #pragma unroll
        for (int ii = 0; ii < 4; ii++)
            #pragma unroll
            for (int jj = 0; jj < 4; jj++)
                lora[ii][jj] = fmaf(a[ii], b[jj], lora[ii][jj]);
    }
    float* out = (type == 0) ? g_q : (type == 1) ? g_k : g_v;
    #pragma unroll
    for (int ii = 0; ii < 4; ii++) {
        int row = rowBase + ty * 4 + ii;
        int b_ = row >> 10, n = row & 1023;
        #pragma unroll
        for (int jj = 0; jj < 4; jj++) {
            int col = colBase + tx * 4 + jj;
            int h = col >> 6, hd = col & 63;
            out[(((b_ * Hq + h) * Nq) + n) * HDq + hd] = fmaf(w, lora[ii][jj], acc[ii][jj]);
        }
    }
}

// ---------------- kernel 3: flash attention per (b,h,qtile) ----------------
__global__ void attn_kernel() {
    extern __shared__ float sm[];
    const int P = 65;
    float* Qs = sm;                 // 64*65
    float* Ks = Qs + 64 * P;
    float* Vs = Ks + 64 * P;
    float* Ss = Vs + 64 * P;
    float* alpha_s = Ss + 64 * P;   // 64
    float* l_s = alpha_s + 64;      // 64

    int t = threadIdx.x;
    int tx = t & 15, ty = t >> 4;
    int qt = blockIdx.x;            // 0..15
    int h = blockIdx.y, b = blockIdx.z;
    const float* Qg = g_q + ((size_t)(b * Hq + h) * Nq + qt * 64) * HDq;
    const float* Kg = g_k + (size_t)(b * Hq + h) * Nq * HDq;
    const float* Vg = g_v + (size_t)(b * Hq + h) * Nq * HDq;

    for (int l = t; l < 64 * 64; l += 256) {
        int m = l >> 6, c = l & 63;
        Qs[m * P + c] = Qg[m * HDq + c];
    }
    float m_i = -1e30f, l_i = 0.f;
    float o[4][4] = {};

    for (int kt = 0; kt < Nq / 64; kt++) {
        for (int l = t; l < 64 * 64; l += 256) {
            int m = l >> 6, c = l & 63;
            Ks[m * P + c] = Kg[(kt * 64 + m) * HDq + c];
            Vs[m * P + c] = Vg[(kt * 64 + m) * HDq + c];
        }
        __syncthreads();
        float s[4][4] = {};
        #pragma unroll 8
        for (int k = 0; k < HDq; k++) {
            float a[4], bb[4];
            #pragma unroll
            for (int ii = 0; ii < 4; ii++) a[ii] = Qs[(ty * 4 + ii) * P + k];
            #pragma unroll
            for (int jj = 0; jj < 4; jj++) bb[jj] = Ks[(tx * 4 + jj) * P + k];
            #pragma unroll
            for (int ii = 0; ii < 4; ii++)
                #pragma unroll
                for (int jj = 0; jj < 4; jj++)
                    s[ii][jj] = fmaf(a[ii], bb[jj], s[ii][jj]);
        }
        #pragma unroll
        for (int ii = 0; ii < 4; ii++)
            #pragma unroll
            for (int jj = 0; jj < 4; jj++)
                Ss[(ty * 4 + ii) * P + tx * 4 + jj] = s[ii][jj] * SCALE;
        __syncthreads();
        if (t < 64) {
            int r = t;
            float mx = m_i;
            #pragma unroll 8
            for (int j = 0; j < 64; j++) mx = fmaxf(mx, Ss[r * P + j]);
            float al = __expf(m_i - mx);
            float sum = 0.f;
            #pragma unroll 8
            for (int j = 0; j < 64; j++) {
                float p = __expf(Ss[r * P + j] - mx);
                Ss[r * P + j] = p;
                sum += p;
            }
            l_i = l_i * al + sum;
            m_i = mx;
            alpha_s[r] = al;
        }
        __syncthreads();
        #pragma unroll
        for (int ii = 0; ii < 4; ii++) {
            float al = alpha_s[ty * 4 + ii];
            #pragma unroll
            for (int jj = 0; jj < 4; jj++) o[ii][jj] *= al;
        }
        #pragma unroll 8
        for (int j = 0; j < 64; j++) {
            float p[4], vv[4];
            #pragma unroll
            for (int ii = 0; ii < 4; ii++) p[ii] = Ss[(ty * 4 + ii) * P + j];
            #pragma unroll
            for (int jj = 0; jj < 4; jj++) vv[jj] = Vs[j * P + tx * 4 + jj];
            #pragma unroll
            for (int ii = 0; ii < 4; ii++)
                #pragma unroll
                for (int jj = 0; jj < 4; jj++)
                    o[ii][jj] = fmaf(p[ii], vv[jj], o[ii][jj]);
        }
        __syncthreads();
    }
    if (t < 64) l_s[t] = l_i;
    __syncthreads();
    #pragma unroll
    for (int ii = 0; ii < 4; ii++) {
        int n = qt * 64 + ty * 4 + ii;
        float inv = 1.f / l_s[ty * 4 + ii];
        #pragma unroll
        for (int jj = 0; jj < 4; jj++) {
            g_att[((size_t)b * Nq + n) * Cq + h * HDq + tx * 4 + jj] = o[ii][jj] * inv;
        }
    }
}

// ---------------- kernel 4: out = att @ Wp + bp ----------------
__global__ void outproj_kernel(const float* __restrict__ W,
                               const float* __restrict__ bias,
                               float* __restrict__ out) {
    __shared__ float As[BK][BM];
    __shared__ float Bs[BK][BN];
    int tx = threadIdx.x & 15, ty = threadIdx.x >> 4;
    int rowBase = blockIdx.y * BM;
    int colBase = blockIdx.x * BN;
    float acc[4][4] = {};
    for (int k0 = 0; k0 < Cq; k0 += BK) {
        #pragma unroll
        for (int i = 0; i < 4; i++) {
            int l = threadIdx.x + 256 * i;
            int m = l >> 4, kk = l & 15;
            As[kk][m] = g_att[(size_t)(rowBase + m) * Cq + k0 + kk];
        }
        #pragma unroll
        for (int i = 0; i < 4; i++) {
            int l = threadIdx.x + 256 * i;
            int col = l & 63, kk = l >> 6;
            Bs[kk][col] = W[(k0 + kk) * Cq + colBase + col];
        }
        __syncthreads();
        #pragma unroll
        for (int kk = 0; kk < BK; kk++) {
            float a[4], b[4];
            #pragma unroll
            for (int ii = 0; ii < 4; ii++) a[ii] = As[kk][ty * 4 + ii];
            #pragma unroll
            for (int jj = 0; jj < 4; jj++) b[jj] = Bs[kk][tx * 4 + jj];
            #pragma unroll
            for (int ii = 0; ii < 4; ii++)
                #pragma unroll
                for (int jj = 0; jj < 4; jj++)
                    acc[ii][jj] = fmaf(a[ii], b[jj], acc[ii][jj]);
        }
        __syncthreads();
    }
    #pragma unroll
    for (int ii = 0; ii < 4; ii++) {
        int row = rowBase + ty * 4 + ii;
        #pragma unroll
        for (int jj = 0; jj < 4; jj++) {
            int col = colBase + tx * 4 + jj;
            out[(size_t)row * Cq + col] = acc[ii][jj] + bias[col];
        }
    }
}

extern "C" void kernel_launch(void* const* d_in, const int* in_sizes, int n_in,
                              void* d_out, int out_size) {
    const float* x    = (const float*)d_in[0];
    const float* Wq   = (const float*)d_in[1];
    const float* Wk   = (const float*)d_in[2];
    const float* Wv   = (const float*)d_in[3];
    const float* Wp   = (const float*)d_in[4];
    const float* bp   = (const float*)d_in[5];
    const float* la_q = (const float*)d_in[6];
    const float* lb_q = (const float*)d_in[7];
    const float* la_k = (const float*)d_in[8];
    const float* lb_k = (const float*)d_in[9];
    const float* la_v = (const float*)d_in[10];
    const float* lb_v = (const float*)d_in[11];
    const float* bw   = (const float*)d_in[12];
    float* out = (float*)d_out;

    lora_xa_kernel<<<ROWS / 16, 256>>>(x, la_q, la_k, la_v);

    dim3 gp(Cq / BN, ROWS / BM);   // (12, 128)
    proj_kernel<<<gp, 256>>>(x, Wq, lb_q, bw, 0);
    proj_kernel<<<gp, 256>>>(x, Wk, lb_k, bw, 1);
    proj_kernel<<<gp, 256>>>(x, Wv, lb_v, bw, 2);

    size_t smem = (size_t)(4 * 64 * 65 + 128) * sizeof(float);  // ~67KB
    cudaFuncSetAttribute(attn_kernel, cudaFuncAttributeMaxDynamicSharedMemorySize, (int)smem);
    attn_kernel<<<dim3(Nq / 64, Hq, Bq), 256, smem>>>();

    outproj_kernel<<<gp, 256>>>(Wp, bp, out);
}

// round 2
// speedup vs baseline: 1.3412x; 1.3412x over previous
#include <cuda_runtime.h>
#include <cuda_bf16.h>

#define Bq 8
#define Nq 1024
#define Cq 768
#define Hq 12
#define HDq 64
#define Rq 16
#define ROWS (Bq*Nq)          // 8192
#define SCALE 0.125f          // 64^-0.5

typedef unsigned long long ull;

// ---------------- f32x2 helpers (sm_103a packed fp32) ----------------
__device__ __forceinline__ ull pk2(float x, float y) {
    ull r;
    asm("mov.b64 %0, {%1, %2};" : "=l"(r) : "r"(__float_as_uint(x)), "r"(__float_as_uint(y)));
    return r;
}
__device__ __forceinline__ ull splat2(float x) { return pk2(x, x); }
__device__ __forceinline__ void upk2(ull v, float& x, float& y) {
    unsigned int a, b;
    asm("mov.b64 {%0, %1}, %2;" : "=r"(a), "=r"(b) : "l"(v));
    x = __uint_as_float(a); y = __uint_as_float(b);
}
__device__ __forceinline__ ull fma2_(ull a, ull b, ull c) {
    ull d;
    asm("fma.rn.f32x2 %0, %1, %2, %3;" : "=l"(d) : "l"(a), "l"(b), "l"(c));
    return d;
}
__device__ __forceinline__ ull mul2_(ull a, ull b) {
    ull d;
    asm("mul.rn.f32x2 %0, %1, %2;" : "=l"(d) : "l"(a), "l"(b));
    return d;
}
__device__ __forceinline__ ull add2_(ull a, ull b) {
    ull d;
    asm("add.rn.f32x2 %0, %1, %2;" : "=l"(d) : "l"(a), "l"(b));
    return d;
}

// ---------------- scratch ----------------
__device__ float g_q[Bq*Hq*Nq*HDq];       // [B,H,N,HD]
__device__ float g_k[Bq*Hq*Nq*HDq];
__device__ float g_v[Bq*Hq*Nq*HDq];
__device__ float g_att[ROWS*Cq];          // [B,N,C]
__device__ float g_xa[3][ROWS*Rq];        // x @ la_{q,k,v}

// ---------------- kernel 1: x @ la for q,k,v ----------------
__global__ void lora_xa_kernel(const float* __restrict__ X,
                               const float* __restrict__ la_q,
                               const float* __restrict__ la_k,
                               const float* __restrict__ la_v) {
    __shared__ float xs[16][Cq];   // 48KB
    int rowBase = blockIdx.x * 16;
    for (int l = threadIdx.x; l < 16 * Cq; l += 256) {
        int r = l / Cq, c = l % Cq;
        xs[r][c] = X[(rowBase + r) * Cq + c];
    }
    __syncthreads();
    int r = threadIdx.x >> 4;
    int c = threadIdx.x & 15;
    float aq = 0.f, ak = 0.f, av = 0.f;
    #pragma unroll 4
    for (int k = 0; k < Cq; k++) {
        float xv = xs[r][k];
        aq = fmaf(xv, la_q[k * Rq + c], aq);
        ak = fmaf(xv, la_k[k * Rq + c], ak);
        av = fmaf(xv, la_v[k * Rq + c], av);
    }
    int row = rowBase + r;
    g_xa[0][row * Rq + c] = aq;
    g_xa[1][row * Rq + c] = ak;
    g_xa[2][row * Rq + c] = av;
}

// ---------------- kernel 2: fused q/k/v projection, 128x128x16, 8x8 micro, f32x2 ----------------
#define PBM 128
#define PBN 128
#define PBK 16
#define PPAD 4

__global__ __launch_bounds__(256) void proj_kernel(
        const float* __restrict__ X,
        const float* __restrict__ Wq, const float* __restrict__ Wk, const float* __restrict__ Wv,
        const float* __restrict__ lbq, const float* __restrict__ lbk, const float* __restrict__ lbv,
        const float* __restrict__ bw) {
    __shared__ float As[PBK][PBM + PPAD];   // K-major A
    __shared__ float Bs[PBK][PBN + PPAD];   // K-major B
    int type = blockIdx.z;
    const float* W  = (type == 0) ? Wq  : (type == 1) ? Wk  : Wv;
    const float* lb = (type == 0) ? lbq : (type == 1) ? lbk : lbv;
    float* out      = (type == 0) ? g_q : (type == 1) ? g_k : g_v;

    int tid = threadIdx.x;
    int tx = tid & 15, ty = tid >> 4;
    int rowBase = blockIdx.y * PBM;
    int colBase = blockIdx.x * PBN;

    ull acc[8][4] = {};

    for (int k0 = 0; k0 < Cq; k0 += PBK) {
        #pragma unroll
        for (int i = 0; i < 2; i++) {
            int l = tid + 256 * i;             // 0..511
            int kc = l & 3, m = l >> 2;
            float4 v = *(const float4*)&X[(size_t)(rowBase + m) * Cq + k0 + kc * 4];
            As[kc * 4 + 0][m] = v.x;
            As[kc * 4 + 1][m] = v.y;
            As[kc * 4 + 2][m] = v.z;
            As[kc * 4 + 3][m] = v.w;
        }
        #pragma unroll
        for (int i = 0; i < 2; i++) {
            int l = tid + 256 * i;
            int nc = l & 31, kk = l >> 5;
            *(float4*)&Bs[kk][nc * 4] =
                *(const float4*)&W[(size_t)(k0 + kk) * Cq + colBase + nc * 4];
        }
        __syncthreads();
        #pragma unroll
        for (int kk = 0; kk < PBK; kk++) {
            float4 a0 = *(const float4*)&As[kk][ty * 8];
            float4 a1 = *(const float4*)&As[kk][ty * 8 + 4];
            ulonglong2 b0 = *(const ulonglong2*)&Bs[kk][tx * 8];
            ulonglong2 b1 = *(const ulonglong2*)&Bs[kk][tx * 8 + 4];
            ull bq[4] = {b0.x, b0.y, b1.x, b1.y};
            float av[8] = {a0.x, a0.y, a0.z, a0.w, a1.x, a1.y, a1.z, a1.w};
            #pragma unroll
            for (int ii = 0; ii < 8; ii++) {
                ull a2 = splat2(av[ii]);
                #pragma unroll
                for (int jp = 0; jp < 4; jp++)
                    acc[ii][jp] = fma2_(a2, bq[jp], acc[ii][jp]);
            }
        }
        __syncthreads();
    }

    // ---- LoRA epilogue: acc += w * (xa @ lb) ----
    float w = bw[type];
    float* xs  = &As[0][0];                  // reuse: 128 x 16 = 2048 floats
    for (int l = tid; l < PBM * Rq; l += 256)
        xs[l] = g_xa[type][(size_t)(rowBase + (l >> 4)) * Rq + (l & 15)];
    for (int l = tid; l < Rq * PBN; l += 256)
        Bs[l >> 7][l & 127] = lb[(size_t)(l >> 7) * Cq + colBase + (l & 127)];
    __syncthreads();

    #pragma unroll
    for (int r = 0; r < Rq; r++) {
        ulonglong2 b0 = *(const ulonglong2*)&Bs[r][tx * 8];
        ulonglong2 b1 = *(const ulonglong2*)&Bs[r][tx * 8 + 4];
        ull bq[4] = {b0.x, b0.y, b1.x, b1.y};
        #pragma unroll
        for (int ii = 0; ii < 8; ii++) {
            float aw = w * xs[(ty * 8 + ii) * Rq + r];
            ull a2 = splat2(aw);
            #pragma unroll
            for (int jp = 0; jp < 4; jp++)
                acc[ii][jp] = fma2_(a2, bq[jp], acc[ii][jp]);
        }
    }

    // ---- write head-split [B,H,N,HD], 8-byte stores ----
    #pragma unroll
    for (int ii = 0; ii < 8; ii++) {
        int row = rowBase + ty * 8 + ii;
        int b_ = row >> 10, n = row & 1023;
        #pragma unroll
        for (int jp = 0; jp < 4; jp++) {
            int col = colBase + tx * 8 + jp * 2;
            int h = col >> 6, hd = col & 63;
            *(ull*)&out[(((size_t)(b_ * Hq + h) * Nq) + n) * HDq + hd] = acc[ii][jp];
        }
    }
}

// ---------------- kernel 3: flash attention, 128q x 128k tiles, f32x2 ----------------
#define SP 132   // padded row of 128
#define VP 68

__global__ __launch_bounds__(256, 1) void attn_kernel() {
    extern __shared__ float sm[];
    float* Qs   = sm;                        // [64][132]  K-major: Qs[c][m]
    float* Ks   = Qs + 64 * SP;              // [64][132]  K-major: Ks[c][j]
    float* Vs   = Ks + 64 * SP;              // [128][68]  Vs[j][n]
    float* Ss   = Vs + 128 * VP;             // [128][132] TRANSPOSED: Ss[j][m]
    float* mrow = Ss + 128 * SP;             // [128]
    float* lrow = mrow + 128;
    float* arow = lrow + 128;

    int tid = threadIdx.x;
    int tx = tid & 15, ty = tid >> 4;
    int qt = blockIdx.x;                     // 0..7 (128-row q tiles)
    int h = blockIdx.y, b = blockIdx.z;
    const float* Qg = g_q + ((size_t)(b * Hq + h) * Nq + qt * 128) * HDq;
    const float* Kg = g_k + (size_t)(b * Hq + h) * Nq * HDq;
    const float* Vg = g_v + (size_t)(b * Hq + h) * Nq * HDq;

    // load Q transposed
    for (int l = tid; l < 128 * 64; l += 256) {
        int m = l >> 6, c = l & 63;
        Qs[c * SP + m] = Qg[m * HDq + c];
    }
    if (tid < 128) { mrow[tid] = -1e30f; lrow[tid] = 0.f; }

    ull op[4][4] = {};                       // O accum: [ncol 0..3][m-pair 0..3]
    const ull sc2 = splat2(SCALE);

    for (int kt = 0; kt < Nq / 128; kt++) {
        __syncthreads();
        for (int l = tid; l < 128 * 64; l += 256) {
            int j = l >> 6, c = l & 63;
            Ks[c * SP + j] = Kg[(kt * 128 + j) * HDq + c];
            Vs[j * VP + c] = Vg[(kt * 128 + j) * HDq + c];
        }
        __syncthreads();

        // S^T[j][m] = K[j,:]·Q[m,:] ; thread: jj = tx*8.., m-pairs ty*8..
        {
            ull sp[8][4] = {};
            #pragma unroll 4
            for (int k = 0; k < HDq; k++) {
                float4 k0v = *(const float4*)&Ks[k * SP + tx * 8];
                float4 k1v = *(const float4*)&Ks[k * SP + tx * 8 + 4];
                ulonglong2 q0 = *(const ulonglong2*)&Qs[k * SP + ty * 8];
                ulonglong2 q1 = *(const ulonglong2*)&Qs[k * SP + ty * 8 + 4];
                ull qp[4] = {q0.x, q0.y, q1.x, q1.y};
                float kv[8] = {k0v.x, k0v.y, k0v.z, k0v.w, k1v.x, k1v.y, k1v.z, k1v.w};
                #pragma unroll
                for (int jj = 0; jj < 8; jj++) {
                    ull kk2 = splat2(kv[jj]);
                    #pragma unroll
                    for (int ip = 0; ip < 4; ip++)
                        sp[jj][ip] = fma2_(kk2, qp[ip], sp[jj][ip]);
                }
            }
            #pragma unroll
            for (int jj = 0; jj < 8; jj++)
                #pragma unroll
                for (int ip = 0; ip < 4; ip++)
                    *(ull*)&Ss[(tx * 8 + jj) * SP + ty * 8 + ip * 2] = mul2_(sp[jj][ip], sc2);
        }
        __syncthreads();

        // online softmax over this 128-key block; 2 threads per query row
        {
            int row = tid >> 1, half = tid & 1;
            int jb = half * 64;
            float mx = -1e30f;
            #pragma unroll 8
            for (int j2 = 0; j2 < 64; j2++)
                mx = fmaxf(mx, Ss[(jb + j2) * SP + row]);
            mx = fmaxf(mx, __shfl_xor_sync(0xffffffffu, mx, 1));
            float mprev = mrow[row];
            float mnew = fmaxf(mprev, mx);
            float sum = 0.f;
            #pragma unroll 8
            for (int j2 = 0; j2 < 64; j2++) {
                float p = __expf(Ss[(jb + j2) * SP + row] - mnew);
                Ss[(jb + j2) * SP + row] = p;
                sum += p;
            }
            sum += __shfl_xor_sync(0xffffffffu, sum, 1);
            if (half == 0) {
                float al = __expf(mprev - mnew);
                mrow[row] = mnew;
                lrow[row] = lrow[row] * al + sum;
                arow[row] = al;
            }
        }
        __syncthreads();

        // rescale O by alpha (per-row pairs), then O += P^T·V
        {
            #pragma unroll
            for (int mp = 0; mp < 4; mp++) {
                ull ap = *(const ull*)&arow[ty * 8 + mp * 2];
                #pragma unroll
                for (int nc = 0; nc < 4; nc++)
                    op[nc][mp] = mul2_(op[nc][mp], ap);
            }
            #pragma unroll 2
            for (int j = 0; j < 128; j++) {
                float4 vv = *(const float4*)&Vs[j * VP + tx * 4];
                ulonglong2 p0 = *(const ulonglong2*)&Ss[j * SP + ty * 8];
                ulonglong2 p1 = *(const ulonglong2*)&Ss[j * SP + ty * 8 + 4];
                ull pf[4] = {p0.x, p0.y, p1.x, p1.y};
                float va[4] = {vv.x, vv.y, vv.z, vv.w};
                #pragma unroll
                for (int nc = 0; nc < 4; nc++) {
                    ull v2 = splat2(va[nc]);
                    #pragma unroll
                    for (int mp = 0; mp < 4; mp++)
                        op[nc][mp] = fma2_(v2, pf[mp], op[nc][mp]);
                }
            }
        }
    }
    __syncthreads();

    // normalize + write to g_att [B,N,C]
    float inv[8];
    #pragma unroll
    for (int r = 0; r < 8; r++) inv[r] = 1.f / lrow[ty * 8 + r];
    #pragma unroll
    for (int nc = 0; nc < 4; nc++) {
        int col = h * HDq + tx * 4 + nc;
        #pragma unroll
        for (int mp = 0; mp < 4; mp++) {
            float o0, o1;
            upk2(op[nc][mp], o0, o1);
            int m0 = ty * 8 + mp * 2;
            size_t row0 = (size_t)b * Nq + qt * 128 + m0;
            g_att[row0 * Cq + col]       = o0 * inv[mp * 2];
            g_att[(row0 + 1) * Cq + col] = o1 * inv[mp * 2 + 1];
        }
    }
}

// ---------------- kernel 4: out = att @ Wp + bp ----------------
__global__ __launch_bounds__(256) void outproj_kernel(const float* __restrict__ W,
                                                      const float* __restrict__ bias,
                                                      float* __restrict__ out) {
    __shared__ float As[PBK][PBM + PPAD];
    __shared__ float Bs[PBK][PBN + PPAD];
    int tid = threadIdx.x;
    int tx = tid & 15, ty = tid >> 4;
    int rowBase = blockIdx.y * PBM;
    int colBase = blockIdx.x * PBN;

    ull acc[8][4] = {};

    for (int k0 = 0; k0 < Cq; k0 += PBK) {
        #pragma unroll
        for (int i = 0; i < 2; i++) {
            int l = tid + 256 * i;
            int kc = l & 3, m = l >> 2;
            float4 v = *(const float4*)&g_att[(size_t)(rowBase + m) * Cq + k0 + kc * 4];
            As[kc * 4 + 0][m] = v.x;
            As[kc * 4 + 1][m] = v.y;
            As[kc * 4 + 2][m] = v.z;
            As[kc * 4 + 3][m] = v.w;
        }
        #pragma unroll
        for (int i = 0; i < 2; i++) {
            int l = tid + 256 * i;
            int nc = l & 31, kk = l >> 5;
            *(float4*)&Bs[kk][nc * 4] =
                *(const float4*)&W[(size_t)(k0 + kk) * Cq + colBase + nc * 4];
        }
        __syncthreads();
        #pragma unroll
        for (int kk = 0; kk < PBK; kk++) {
            float4 a0 = *(const float4*)&As[kk][ty * 8];
            float4 a1 = *(const float4*)&As[kk][ty * 8 + 4];
            ulonglong2 b0 = *(const ulonglong2*)&Bs[kk][tx * 8];
            ulonglong2 b1 = *(const ulonglong2*)&Bs[kk][tx * 8 + 4];
            ull bq[4] = {b0.x, b0.y, b1.x, b1.y};
            float av[8] = {a0.x, a0.y, a0.z, a0.w, a1.x, a1.y, a1.z, a1.w};
            #pragma unroll
            for (int ii = 0; ii < 8; ii++) {
                ull a2 = splat2(av[ii]);
                #pragma unroll
                for (int jp = 0; jp < 4; jp++)
                    acc[ii][jp] = fma2_(a2, bq[jp], acc[ii][jp]);
            }
        }
        __syncthreads();
    }

    #pragma unroll
    for (int ii = 0; ii < 8; ii++) {
        int row = rowBase + ty * 8 + ii;
        #pragma unroll
        for (int jp = 0; jp < 4; jp++) {
            int col = colBase + tx * 8 + jp * 2;
            ull bv = *(const ull*)&bias[col];
            *(ull*)&out[(size_t)row * Cq + col] = add2_(acc[ii][jp], bv);
        }
    }
}

extern "C" void kernel_launch(void* const* d_in, const int* in_sizes, int n_in,
                              void* d_out, int out_size) {
    const float* x    = (const float*)d_in[0];
    const float* Wq   = (const float*)d_in[1];
    const float* Wk   = (const float*)d_in[2];
    const float* Wv   = (const float*)d_in[3];
    const float* Wp   = (const float*)d_in[4];
    const float* bp   = (const float*)d_in[5];
    const float* la_q = (const float*)d_in[6];
    const float* lb_q = (const float*)d_in[7];
    const float* la_k = (const float*)d_in[8];
    const float* lb_k = (const float*)d_in[9];
    const float* la_v = (const float*)d_in[10];
    const float* lb_v = (const float*)d_in[11];
    const float* bw   = (const float*)d_in[12];
    float* out = (float*)d_out;

    lora_xa_kernel<<<ROWS / 16, 256>>>(x, la_q, la_k, la_v);

    dim3 gp(Cq / PBN, ROWS / PBM, 3);       // (6, 64, 3)
    proj_kernel<<<gp, 256>>>(x, Wq, Wk, Wv, lb_q, lb_k, lb_v, bw);

    size_t smem = (size_t)(64 * SP + 64 * SP + 128 * VP + 128 * SP + 3 * 128) * sizeof(float);
    cudaFuncSetAttribute(attn_kernel, cudaFuncAttributeMaxDynamicSharedMemorySize, (int)smem);
    attn_kernel<<<dim3(Nq / 128, Hq, Bq), 256, smem>>>();

    dim3 go(Cq / PBN, ROWS / PBM);          // (6, 64)
    outproj_kernel<<<go, 256>>>(Wp, bp, out);
}